// round 2
// baseline (speedup 1.0000x reference)
#include <cuda_runtime.h>
#include <cstdint>

#define FULLMASK 0xffffffffu
#define L2E 1.4426950408889634f

static __device__ __forceinline__ float ex2f_(float x) {
    float r; asm("ex2.approx.f32 %0, %1;" : "=f"(r) : "f"(x)); return r;
}
static __device__ __forceinline__ float rcpf_(float x) {
    float r; asm("rcp.approx.f32 %0, %1;" : "=f"(r) : "f"(x)); return r;
}

// Unified gate activation:
//   sigmoid(x) = 1 - 1/(1+e^x)      (kk = L2E,  mm = 1)
//   tanh(x)    = 1 - 2/(1+e^{2x})   (kk = 2L2E, mm = 2)
// ex2.approx / rcp.approx rel err ~1e-7 -> safe over 2048 recurrent steps.
static __device__ __forceinline__ float gate_act(float x, float kk, float mm) {
    float u = ex2f_(kk * x);
    float r = rcpf_(1.0f + u);
    return fmaf(-mm, r, 1.0f);
}
static __device__ __forceinline__ float tanh_acc(float x) {
    return gate_act(x, 2.0f * L2E, 2.0f);
}

// acc: this lane's gate preactivation (lane g in [0,32): i=0-7, f=8-15, g=16-23, o=24-31)
// returns new h (valid on lanes 0-7), updates c (valid on lanes 0-7)
static __device__ __forceinline__ float cell_update(float acc, float& c, float kk, float mm) {
    float g  = gate_act(acc, kk, mm);
    float fg = __shfl_down_sync(FULLMASK, g, 8);   // f for lanes 0-7
    float gg = __shfl_down_sync(FULLMASK, g, 16);  // g for lanes 0-7
    float og = __shfl_down_sync(FULLMASK, g, 24);  // o for lanes 0-7
    c = fmaf(fg, c, g * gg);                        // c = f*c + i*g
    return og * tanh_acc(c);                        // h = o*tanh(c)
}

static __device__ __forceinline__ void load8(float* d, const float* p) {
    float4 a = *(const float4*)(p);
    float4 b = *(const float4*)(p + 4);
    d[0] = a.x; d[1] = a.y; d[2] = a.z; d[3] = a.w;
    d[4] = b.x; d[5] = b.y; d[6] = b.z; d[7] = b.w;
}

__global__ void __launch_bounds__(128)
rnn_ac_kernel(const float* __restrict__ seq, const int* __restrict__ lengths,
              const float* __restrict__ Wih0, const float* __restrict__ Whh0,
              const float* __restrict__ bih0, const float* __restrict__ bhh0,
              const float* __restrict__ Wih1, const float* __restrict__ Whh1,
              const float* __restrict__ bih1, const float* __restrict__ bhh1,
              const float* __restrict__ Wl,  const float* __restrict__ bl,
              const float* __restrict__ Wv,  const float* __restrict__ bv,
              const float* __restrict__ Wa,  const float* __restrict__ ba,
              const float* __restrict__ log_std,
              float* __restrict__ out, int B, int S)
{
    const int warp = (blockIdx.x * blockDim.x + threadIdx.x) >> 5;
    const int lane = threadIdx.x & 31;
    if (warp >= B) return;
    const int b = warp;

    // per-lane gate weights (rows of Wih/Whh), registers
    float wi0[8], wh0[8], wi1[8], wh1[8];
    {
        const float4* p;
        p = (const float4*)(Wih0 + lane * 8);
        float4 a = p[0], q = p[1];
        wi0[0]=a.x; wi0[1]=a.y; wi0[2]=a.z; wi0[3]=a.w; wi0[4]=q.x; wi0[5]=q.y; wi0[6]=q.z; wi0[7]=q.w;
        p = (const float4*)(Whh0 + lane * 8);
        a = p[0]; q = p[1];
        wh0[0]=a.x; wh0[1]=a.y; wh0[2]=a.z; wh0[3]=a.w; wh0[4]=q.x; wh0[5]=q.y; wh0[6]=q.z; wh0[7]=q.w;
        p = (const float4*)(Wih1 + lane * 8);
        a = p[0]; q = p[1];
        wi1[0]=a.x; wi1[1]=a.y; wi1[2]=a.z; wi1[3]=a.w; wi1[4]=q.x; wi1[5]=q.y; wi1[6]=q.z; wi1[7]=q.w;
        p = (const float4*)(Whh1 + lane * 8);
        a = p[0]; q = p[1];
        wh1[0]=a.x; wh1[1]=a.y; wh1[2]=a.z; wh1[3]=a.w; wh1[4]=q.x; wh1[5]=q.y; wh1[6]=q.z; wh1[7]=q.w;
    }
    const float b0 = bih0[lane] + bhh0[lane];
    const float b1 = bih1[lane] + bhh1[lane];

    // gate type: lanes 16-23 are the 'g' (tanh) gate, others sigmoid
    const bool isg = ((lane >> 3) == 2);
    const float kk = isg ? 2.0f * L2E : L2E;
    const float mm = isg ? 2.0f : 1.0f;

    float h0a[8], h1a[8];
#pragma unroll
    for (int k = 0; k < 8; k++) { h0a[k] = 0.0f; h1a[k] = 0.0f; }
    float c0 = 0.0f, c1 = 0.0f;

    const int L = lengths[b];
    const float* xbase = seq + (size_t)b * (size_t)S * 8;

    float x0[8];
    load8(x0, xbase);  // x_0

    // ---- prologue: layer0 step 0 (h0 state is zero -> skip h-dot) ----
    {
        float a0 = b0;
#pragma unroll
        for (int k = 0; k < 8; k++) a0 = fmaf(wi0[k], x0[k], a0);
        float h0n = cell_update(a0, c0, kk, mm);
#pragma unroll
        for (int k = 0; k < 8; k++) h0a[k] = __shfl_sync(FULLMASK, h0n, k);
    }

    // preload x_1 (clamped if L==1; value unused then)
    {
        int tn = (1 < L) ? 1 : (L - 1);
        load8(x0, xbase + (size_t)tn * 8);
    }

    // ---- steady state: iteration t runs layer1(t-1) and layer0(t) together ----
    for (int t = 1; t < L; t++) {
        // prefetch x_{t+1} (clamped on last iter)
        float xn[8];
        {
            int tn = (t + 1 < L) ? (t + 1) : (L - 1);
            load8(xn, xbase + (size_t)tn * 8);
        }

        // layer1 step t-1 accumulation (reads h0a = h0_{t-1}, h1a = h1_{t-2})
        float a1 = b1;
#pragma unroll
        for (int k = 0; k < 8; k++) a1 = fmaf(wi1[k], h0a[k], a1);
#pragma unroll
        for (int k = 0; k < 8; k++) a1 = fmaf(wh1[k], h1a[k], a1);

        // layer0 step t accumulation (reads x_t, h0a = h0_{t-1})
        float a0 = b0;
#pragma unroll
        for (int k = 0; k < 8; k++) a0 = fmaf(wi0[k], x0[k], a0);
#pragma unroll
        for (int k = 0; k < 8; k++) a0 = fmaf(wh0[k], h0a[k], a0);

        // two independent update chains -> ptxas interleaves them
        float h1n = cell_update(a1, c1, kk, mm);
        float h0n = cell_update(a0, c0, kk, mm);

#pragma unroll
        for (int k = 0; k < 8; k++) h1a[k] = __shfl_sync(FULLMASK, h1n, k);
#pragma unroll
        for (int k = 0; k < 8; k++) h0a[k] = __shfl_sync(FULLMASK, h0n, k);

#pragma unroll
        for (int k = 0; k < 8; k++) x0[k] = xn[k];
    }

    // ---- epilogue: layer1 step L-1 ----
    {
        float a1 = b1;
#pragma unroll
        for (int k = 0; k < 8; k++) a1 = fmaf(wi1[k], h0a[k], a1);
#pragma unroll
        for (int k = 0; k < 8; k++) a1 = fmaf(wh1[k], h1a[k], a1);
        float h1n = cell_update(a1, c1, kk, mm);
#pragma unroll
        for (int k = 0; k < 8; k++) h1a[k] = __shfl_sync(FULLMASK, h1n, k);
    }

    // ---- heads: feat = tanh(y @ Wl^T + bl); value; mean; log_std; std ----
    // every lane has h1a; compute feat redundantly (no shuffles needed)
    float feat[4];
#pragma unroll
    for (int j = 0; j < 4; j++) {
        float a = bl[j];
#pragma unroll
        for (int k = 0; k < 8; k++) a = fmaf(Wl[j * 8 + k], h1a[k], a);
        feat[j] = tanh_acc(a);
    }

    if (lane == 0) {
        float v = bv[0];
#pragma unroll
        for (int j = 0; j < 4; j++) v = fmaf(Wv[j], feat[j], v);
        out[b] = v;                                   // value [B,1]
    }
    if (lane < 4) {
        float m = ba[lane];
#pragma unroll
        for (int j = 0; j < 4; j++) m = fmaf(Wa[lane * 4 + j], feat[j], m);
        out[B + b * 4 + lane] = m;                    // action_mean [B,4]
        float ls = log_std[lane];
        out[5 * B + b * 4 + lane] = ls;               // action_log_std [B,4]
        out[9 * B + b * 4 + lane] = ex2f_(ls * L2E);  // action_std = exp(ls)
    }
}

extern "C" void kernel_launch(void* const* d_in, const int* in_sizes, int n_in,
                              void* d_out, int out_size)
{
    const float* seq     = (const float*)d_in[0];
    const int*   lengths = (const int*)d_in[1];
    const float* Wih0 = (const float*)d_in[2];
    const float* Whh0 = (const float*)d_in[3];
    const float* bih0 = (const float*)d_in[4];
    const float* bhh0 = (const float*)d_in[5];
    const float* Wih1 = (const float*)d_in[6];
    const float* Whh1 = (const float*)d_in[7];
    const float* bih1 = (const float*)d_in[8];
    const float* bhh1 = (const float*)d_in[9];
    const float* Wl = (const float*)d_in[10];
    const float* bl = (const float*)d_in[11];
    const float* Wv = (const float*)d_in[12];
    const float* bv = (const float*)d_in[13];
    const float* Wa = (const float*)d_in[14];
    const float* ba = (const float*)d_in[15];
    const float* ls = (const float*)d_in[16];
    float* out = (float*)d_out;

    int B = in_sizes[1];
    int S = in_sizes[0] / (B * 8);

    int threads = 128;                       // 4 warps/CTA, 1 sequence per warp
    int grid = (B * 32 + threads - 1) / threads;
    rnn_ac_kernel<<<grid, threads>>>(seq, lengths, Wih0, Whh0, bih0, bhh0,
                                     Wih1, Whh1, bih1, bhh1,
                                     Wl, bl, Wv, bv, Wa, ba, ls, out, B, S);
}

// round 3
// speedup vs baseline: 1.0204x; 1.0204x over previous
#include <cuda_runtime.h>
#include <cstdint>

#define FULLMASK 0xffffffffu
#define L2E 1.4426950408889634f

static __device__ __forceinline__ float ex2f_(float x) {
    float r; asm("ex2.approx.f32 %0, %1;" : "=f"(r) : "f"(x)); return r;
}
static __device__ __forceinline__ float rcpf_(float x) {
    float r; asm("rcp.approx.f32 %0, %1;" : "=f"(r) : "f"(x)); return r;
}

// sigmoid(x) = 1 - 1/(1+e^x)   (kk = L2E,  mm = 1)
// tanh(x)    = 1 - 2/(1+e^2x)  (kk = 2L2E, mm = 2)
static __device__ __forceinline__ float gate_act(float x, float kk, float mm) {
    float u = ex2f_(kk * x);
    float r = rcpf_(1.0f + u);
    return fmaf(-mm, r, 1.0f);
}
static __device__ __forceinline__ float tanh_acc(float x) {
    return gate_act(x, 2.0f * L2E, 2.0f);
}

// ---- packed f32x2 helpers (sm_103a FFMA2) ----
static __device__ __forceinline__ uint64_t pk(float lo, float hi) {
    uint64_t r; asm("mov.b64 %0, {%1,%2};" : "=l"(r) : "f"(lo), "f"(hi)); return r;
}
static __device__ __forceinline__ void upk(uint64_t p, float& lo, float& hi) {
    asm("mov.b64 {%0,%1}, %2;" : "=f"(lo), "=f"(hi) : "l"(p));
}
static __device__ __forceinline__ uint64_t fma2(uint64_t a, uint64_t b, uint64_t c) {
    uint64_t d; asm("fma.rn.f32x2 %0, %1, %2, %3;" : "=l"(d) : "l"(a), "l"(b), "l"(c));
    return d;
}
static __device__ __forceinline__ float hadd2(uint64_t p) {
    float lo, hi; upk(p, lo, hi); return lo + hi;
}
// load 8 consecutive floats, packed into 4 f32x2 carriers
static __device__ __forceinline__ void load8p(uint64_t* d, const float* p) {
    float4 a = *(const float4*)(p);
    float4 b = *(const float4*)(p + 4);
    d[0] = pk(a.x, a.y); d[1] = pk(a.z, a.w);
    d[2] = pk(b.x, b.y); d[3] = pk(b.z, b.w);
}

__global__ void __launch_bounds__(128)
rnn_ac_kernel(const float* __restrict__ seq, const int* __restrict__ lengths,
              const float* __restrict__ Wih0, const float* __restrict__ Whh0,
              const float* __restrict__ bih0, const float* __restrict__ bhh0,
              const float* __restrict__ Wih1, const float* __restrict__ Whh1,
              const float* __restrict__ bih1, const float* __restrict__ bhh1,
              const float* __restrict__ Wl,  const float* __restrict__ bl,
              const float* __restrict__ Wv,  const float* __restrict__ bv,
              const float* __restrict__ Wa,  const float* __restrict__ ba,
              const float* __restrict__ log_std,
              float* __restrict__ out, int B, int S)
{
    __shared__ float hsh[4][16];   // per-warp: [0:8)=h0, [8:16)=h1

    const int warp = (blockIdx.x * blockDim.x + threadIdx.x) >> 5;
    const int lane = threadIdx.x & 31;
    const int wI   = threadIdx.x >> 5;
    if (warp >= B) return;
    const int b = warp;
    float* hw = hsh[wI];

    // per-lane gate weight rows, packed f32x2
    uint64_t wi0p[4], wh0p[4], wi1p[4], wh1p[4];
    load8p(wi0p, Wih0 + lane * 8);
    load8p(wh0p, Whh0 + lane * 8);
    load8p(wi1p, Wih1 + lane * 8);
    load8p(wh1p, Whh1 + lane * 8);
    const float b0 = bih0[lane] + bhh0[lane];
    const float b1 = bih1[lane] + bhh1[lane];

    // lanes 16-23 carry the tanh ('g') gate
    const bool  isg = ((lane >> 3) == 2);
    const float kk  = isg ? 2.0f * L2E : L2E;
    const float mm  = isg ? 2.0f : 1.0f;

    uint64_t h0p[4], h1p[4];
#pragma unroll
    for (int k = 0; k < 4; k++) { h0p[k] = 0; h1p[k] = 0; }
    float c0 = 0.0f, c1 = 0.0f;

    const int L = lengths[b];
    const float* xbase = seq + (size_t)b * (size_t)S * 8;

    uint64_t xp[4];
    load8p(xp, xbase);   // x_0

    // ---- prologue: layer0 step 0 (h0 = 0 -> x-dot only) ----
    {
        uint64_t a0p = pk(b0, 0.0f);
#pragma unroll
        for (int k = 0; k < 4; k++) a0p = fma2(wi0p[k], xp[k], a0p);
        float a0 = hadd2(a0p);
        float g0v = gate_act(a0, kk, mm);
        float fg = __shfl_down_sync(FULLMASK, g0v, 8);
        float gg = __shfl_down_sync(FULLMASK, g0v, 16);
        float og = __shfl_down_sync(FULLMASK, g0v, 24);
        c0 = fmaf(fg, c0, g0v * gg);
        float h0n = og * tanh_acc(c0);
        if (lane < 8) { hw[lane] = h0n; hw[8 + lane] = 0.0f; }
        __syncwarp();
        float4 v;
        v = *(const float4*)&hw[0]; h0p[0] = pk(v.x, v.y); h0p[1] = pk(v.z, v.w);
        v = *(const float4*)&hw[4]; h0p[2] = pk(v.x, v.y); h0p[3] = pk(v.z, v.w);
        // h1p stays zero
    }

    // preload x_1 (clamped; unused if L==1)
    load8p(xp, xbase + (size_t)min(1, L - 1) * 8);

    // ---- steady state: iteration t runs layer1(t-1) and layer0(t) ----
#pragma unroll 2
    for (int t = 1; t < L; t++) {
        // prefetch next x into regs (t+1) and a line ahead into L2
        uint64_t xnp[4];
        load8p(xnp, xbase + (size_t)min(t + 1, L - 1) * 8);
        asm volatile("prefetch.global.L2 [%0];"
                     :: "l"(xbase + (size_t)min(t + 4, L - 1) * 8));

        // layer1 accumulation (h0p = h0(t-1), h1p = h1(t-2))
        uint64_t a1p = pk(b1, 0.0f);
#pragma unroll
        for (int k = 0; k < 4; k++) a1p = fma2(wi1p[k], h0p[k], a1p);
#pragma unroll
        for (int k = 0; k < 4; k++) a1p = fma2(wh1p[k], h1p[k], a1p);

        // layer0 accumulation (x_t, h0(t-1))
        uint64_t a0p = pk(b0, 0.0f);
#pragma unroll
        for (int k = 0; k < 4; k++) a0p = fma2(wi0p[k], xp[k], a0p);
#pragma unroll
        for (int k = 0; k < 4; k++) a0p = fma2(wh0p[k], h0p[k], a0p);

        float a1 = hadd2(a1p);
        float a0 = hadd2(a0p);

        // gate activations (two independent chains)
        float g1v = gate_act(a1, kk, mm);
        float g0v = gate_act(a0, kk, mm);

        float fg1 = __shfl_down_sync(FULLMASK, g1v, 8);
        float gg1 = __shfl_down_sync(FULLMASK, g1v, 16);
        float og1 = __shfl_down_sync(FULLMASK, g1v, 24);
        float fg0 = __shfl_down_sync(FULLMASK, g0v, 8);
        float gg0 = __shfl_down_sync(FULLMASK, g0v, 16);
        float og0 = __shfl_down_sync(FULLMASK, g0v, 24);

        c1 = fmaf(fg1, c1, g1v * gg1);
        c0 = fmaf(fg0, c0, g0v * gg0);

        // merged tanh: lanes 0-7 evaluate tanh(c0), lanes 8-15 tanh(c1)
        float c1s = __shfl_sync(FULLMASK, c1, lane & 7);
        float cc  = (lane < 8) ? c0 : c1s;
        float tc  = tanh_acc(cc);
        float t1  = __shfl_down_sync(FULLMASK, tc, 8);  // tanh(c1) -> lanes 0-7
        float h0n = og0 * tc;
        float h1n = og1 * t1;

        // broadcast h0,h1 via shared memory (1 warp's private 64B)
        if (lane < 8) { hw[lane] = h0n; hw[8 + lane] = h1n; }
        __syncwarp();
        float4 v;
        v = *(const float4*)&hw[0];  h0p[0] = pk(v.x, v.y); h0p[1] = pk(v.z, v.w);
        v = *(const float4*)&hw[4];  h0p[2] = pk(v.x, v.y); h0p[3] = pk(v.z, v.w);
        v = *(const float4*)&hw[8];  h1p[0] = pk(v.x, v.y); h1p[1] = pk(v.z, v.w);
        v = *(const float4*)&hw[12]; h1p[2] = pk(v.x, v.y); h1p[3] = pk(v.z, v.w);

#pragma unroll
        for (int k = 0; k < 4; k++) xp[k] = xnp[k];
    }

    // ---- epilogue: layer1 step L-1 ----
    float h1a[8];
    {
        uint64_t a1p = pk(b1, 0.0f);
#pragma unroll
        for (int k = 0; k < 4; k++) a1p = fma2(wi1p[k], h0p[k], a1p);
#pragma unroll
        for (int k = 0; k < 4; k++) a1p = fma2(wh1p[k], h1p[k], a1p);
        float a1 = hadd2(a1p);
        float g1v = gate_act(a1, kk, mm);
        float fg = __shfl_down_sync(FULLMASK, g1v, 8);
        float gg = __shfl_down_sync(FULLMASK, g1v, 16);
        float og = __shfl_down_sync(FULLMASK, g1v, 24);
        c1 = fmaf(fg, c1, g1v * gg);
        float h1n = og * tanh_acc(c1);
#pragma unroll
        for (int k = 0; k < 8; k++) h1a[k] = __shfl_sync(FULLMASK, h1n, k);
    }

    // ---- heads ----
    float feat[4];
#pragma unroll
    for (int j = 0; j < 4; j++) {
        float a = bl[j];
#pragma unroll
        for (int k = 0; k < 8; k++) a = fmaf(Wl[j * 8 + k], h1a[k], a);
        feat[j] = tanh_acc(a);
    }

    if (lane == 0) {
        float v = bv[0];
#pragma unroll
        for (int j = 0; j < 4; j++) v = fmaf(Wv[j], feat[j], v);
        out[b] = v;                                   // value [B,1]
    }
    if (lane < 4) {
        float m = ba[lane];
#pragma unroll
        for (int j = 0; j < 4; j++) m = fmaf(Wa[lane * 4 + j], feat[j], m);
        out[B + b * 4 + lane] = m;                    // action_mean [B,4]
        float ls = log_std[lane];
        out[5 * B + b * 4 + lane] = ls;               // action_log_std [B,4]
        out[9 * B + b * 4 + lane] = ex2f_(ls * L2E);  // action_std [B,4]
    }
}

extern "C" void kernel_launch(void* const* d_in, const int* in_sizes, int n_in,
                              void* d_out, int out_size)
{
    const float* seq     = (const float*)d_in[0];
    const int*   lengths = (const int*)d_in[1];
    const float* Wih0 = (const float*)d_in[2];
    const float* Whh0 = (const float*)d_in[3];
    const float* bih0 = (const float*)d_in[4];
    const float* bhh0 = (const float*)d_in[5];
    const float* Wih1 = (const float*)d_in[6];
    const float* Whh1 = (const float*)d_in[7];
    const float* bih1 = (const float*)d_in[8];
    const float* bhh1 = (const float*)d_in[9];
    const float* Wl = (const float*)d_in[10];
    const float* bl = (const float*)d_in[11];
    const float* Wv = (const float*)d_in[12];
    const float* bv = (const float*)d_in[13];
    const float* Wa = (const float*)d_in[14];
    const float* ba = (const float*)d_in[15];
    const float* ls = (const float*)d_in[16];
    float* out = (float*)d_out;

    int B = in_sizes[1];
    int S = in_sizes[0] / (B * 8);

    int threads = 128;                       // 4 warps/CTA, 1 sequence per warp
    int grid = (B * 32 + threads - 1) / threads;
    rnn_ac_kernel<<<grid, threads>>>(seq, lengths, Wih0, Whh0, bih0, bhh0,
                                     Wih1, Whh1, bih1, bhh1,
                                     Wl, bl, Wv, bv, Wa, ba, ls, out, B, S);
}

// round 4
// speedup vs baseline: 1.6421x; 1.6093x over previous
#include <cuda_runtime.h>
#include <cstdint>

#define FULLMASK 0xffffffffu
#define L2E 1.4426950408889634f
#define MAXB 8192

static __device__ int g_perm[MAXB];

static __device__ __forceinline__ float ex2f_(float x) {
    float r; asm("ex2.approx.f32 %0, %1;" : "=f"(r) : "f"(x)); return r;
}
static __device__ __forceinline__ float rcpf_(float x) {
    float r; asm("rcp.approx.f32 %0, %1;" : "=f"(r) : "f"(x)); return r;
}

// sigmoid(x) = 1 - 1/(1+e^x)   (kk = L2E,  mm = 1)
// tanh(x)    = 1 - 2/(1+e^2x)  (kk = 2L2E, mm = 2)
static __device__ __forceinline__ float gate_act(float x, float kk, float mm) {
    float u = ex2f_(kk * x);
    float r = rcpf_(1.0f + u);
    return fmaf(-mm, r, 1.0f);
}
static __device__ __forceinline__ float tanh_acc(float x) {
    return gate_act(x, 2.0f * L2E, 2.0f);
}

// ---- packed f32x2 helpers (sm_103a) ----
static __device__ __forceinline__ uint64_t pk(float lo, float hi) {
    uint64_t r; asm("mov.b64 %0, {%1,%2};" : "=l"(r) : "f"(lo), "f"(hi)); return r;
}
static __device__ __forceinline__ uint64_t fma2(uint64_t a, uint64_t b, uint64_t c) {
    uint64_t d; asm("fma.rn.f32x2 %0, %1, %2, %3;" : "=l"(d) : "l"(a), "l"(b), "l"(c));
    return d;
}
static __device__ __forceinline__ uint64_t add2(uint64_t a, uint64_t b) {
    uint64_t d; asm("add.rn.f32x2 %0, %1, %2;" : "=l"(d) : "l"(a), "l"(b));
    return d;
}
static __device__ __forceinline__ float hadd2(uint64_t p) {
    float lo, hi; asm("mov.b64 {%0,%1}, %2;" : "=f"(lo), "=f"(hi) : "l"(p));
    return lo + hi;
}
static __device__ __forceinline__ void load8p(uint64_t* d, const float* p) {
    float4 a = *(const float4*)(p);
    float4 b = *(const float4*)(p + 4);
    d[0] = pk(a.x, a.y); d[1] = pk(a.z, a.w);
    d[2] = pk(b.x, b.y); d[3] = pk(b.z, b.w);
}
// broadcast h (valid on lanes 0-7) to 4 packed pairs on every lane
static __device__ __forceinline__ void bcast_pack(uint64_t* d, float h) {
#pragma unroll
    for (int k = 0; k < 4; k++) {
        float lo = __shfl_sync(FULLMASK, h, 2 * k);
        float hi = __shfl_sync(FULLMASK, h, 2 * k + 1);
        d[k] = pk(lo, hi);
    }
}

// ---- rank-by-counting: perm[rank] = idx, descending length ----
__global__ void rank_kernel(const int* __restrict__ lengths, int B) {
    __shared__ int sl[4096];
    int tid = threadIdx.x;
    for (int j = tid; j < B; j += blockDim.x) sl[j] = lengths[j];
    __syncthreads();
    int idx = blockIdx.x * blockDim.x + tid;
    if (idx >= B) return;
    int L = sl[idx];
    int rank = 0;
    for (int j = 0; j < B; j++) {
        int lj = sl[j];
        rank += (lj > L) || (lj == L && j < idx);
    }
    g_perm[rank] = idx;
}

__global__ void __launch_bounds__(128)
rnn_ac_kernel(const float* __restrict__ seq, const int* __restrict__ lengths,
              const float* __restrict__ Wih0, const float* __restrict__ Whh0,
              const float* __restrict__ bih0, const float* __restrict__ bhh0,
              const float* __restrict__ Wih1, const float* __restrict__ Whh1,
              const float* __restrict__ bih1, const float* __restrict__ bhh1,
              const float* __restrict__ Wl,  const float* __restrict__ bl,
              const float* __restrict__ Wv,  const float* __restrict__ bv,
              const float* __restrict__ Wa,  const float* __restrict__ ba,
              const float* __restrict__ log_std,
              float* __restrict__ out, int B, int S, int use_perm)
{
    const int warp = (blockIdx.x * blockDim.x + threadIdx.x) >> 5;
    const int lane = threadIdx.x & 31;
    if (warp >= B) return;
    const int b = use_perm ? g_perm[warp] : warp;

    // per-lane gate weight rows, packed f32x2
    uint64_t wi0p[4], wh0p[4], wi1p[4], wh1p[4];
    load8p(wi0p, Wih0 + lane * 8);
    load8p(wh0p, Whh0 + lane * 8);
    load8p(wi1p, Wih1 + lane * 8);
    load8p(wh1p, Whh1 + lane * 8);
    const uint64_t b0p = pk(bih0[lane] + bhh0[lane], 0.0f);
    const uint64_t b1p = pk(bih1[lane] + bhh1[lane], 0.0f);
    const uint64_t z64 = pk(0.0f, 0.0f);

    // lanes 16-23 carry the tanh ('g') gate
    const bool  isg = ((lane >> 3) == 2);
    const float kk  = isg ? 2.0f * L2E : L2E;
    const float mm  = isg ? 2.0f : 1.0f;

    uint64_t h0p[4], h1p[4];
#pragma unroll
    for (int k = 0; k < 4; k++) { h0p[k] = z64; h1p[k] = z64; }
    float c0 = 0.0f, c1 = 0.0f;

    const int L = lengths[b];
    const float* xbase = seq + (size_t)b * (size_t)S * 8;

    uint64_t xp[4];
    load8p(xp, xbase);   // x_0

    // ---- prologue: layer0 step 0 (h0 = 0 -> x-dot only) ----
    {
        uint64_t aA = fma2(wi0p[0], xp[0], b0p);
        uint64_t aB = fma2(wi0p[1], xp[1], z64);
        aA = fma2(wi0p[2], xp[2], aA);
        aB = fma2(wi0p[3], xp[3], aB);
        float a0 = hadd2(add2(aA, aB));
        float g0v = gate_act(a0, kk, mm);
        float fg = __shfl_down_sync(FULLMASK, g0v, 8);
        float gg = __shfl_down_sync(FULLMASK, g0v, 16);
        float og = __shfl_down_sync(FULLMASK, g0v, 24);
        c0 = fmaf(fg, c0, g0v * gg);
        float h0n = og * tanh_acc(c0);
        bcast_pack(h0p, h0n);
    }

    load8p(xp, xbase + (size_t)min(1, L - 1) * 8);   // x_1 (clamped)

    // ---- steady state: iteration t runs layer1(t-1) and layer0(t) ----
    for (int t = 1; t < L; t++) {
        uint64_t xnp[4];
        load8p(xnp, xbase + (size_t)min(t + 1, L - 1) * 8);
        asm volatile("prefetch.global.L2 [%0];"
                     :: "l"(xbase + (size_t)min(t + 4, L - 1) * 8));

        // layer1 acc (h0p = h0(t-1), h1p = h1(t-2)) — off the binding chain
        uint64_t a1A = fma2(wi1p[0], h0p[0], b1p);
        uint64_t a1B = fma2(wi1p[1], h0p[1], z64);
        a1A = fma2(wi1p[2], h0p[2], a1A);
        a1B = fma2(wi1p[3], h0p[3], a1B);
        a1A = fma2(wh1p[0], h1p[0], a1A);
        a1B = fma2(wh1p[1], h1p[1], a1B);
        a1A = fma2(wh1p[2], h1p[2], a1A);
        a1B = fma2(wh1p[3], h1p[3], a1B);
        float a1 = hadd2(add2(a1A, a1B));

        // layer0 acc: x-part first (off-chain), h-part last (on-chain, depth 2)
        uint64_t a0A = fma2(wi0p[0], xp[0], b0p);
        uint64_t a0B = fma2(wi0p[1], xp[1], z64);
        a0A = fma2(wi0p[2], xp[2], a0A);
        a0B = fma2(wi0p[3], xp[3], a0B);
        a0A = fma2(wh0p[0], h0p[0], a0A);
        a0B = fma2(wh0p[1], h0p[1], a0B);
        a0A = fma2(wh0p[2], h0p[2], a0A);
        a0B = fma2(wh0p[3], h0p[3], a0B);
        float a0 = hadd2(add2(a0A, a0B));

        // two independent activation/update chains
        float g0v = gate_act(a0, kk, mm);
        float g1v = gate_act(a1, kk, mm);

        float fg0 = __shfl_down_sync(FULLMASK, g0v, 8);
        float gg0 = __shfl_down_sync(FULLMASK, g0v, 16);
        float og0 = __shfl_down_sync(FULLMASK, g0v, 24);
        float fg1 = __shfl_down_sync(FULLMASK, g1v, 8);
        float gg1 = __shfl_down_sync(FULLMASK, g1v, 16);
        float og1 = __shfl_down_sync(FULLMASK, g1v, 24);

        c0 = fmaf(fg0, c0, g0v * gg0);
        c1 = fmaf(fg1, c1, g1v * gg1);
        float h0n = og0 * tanh_acc(c0);
        float h1n = og1 * tanh_acc(c1);

        bcast_pack(h0p, h0n);
        bcast_pack(h1p, h1n);

#pragma unroll
        for (int k = 0; k < 4; k++) xp[k] = xnp[k];
    }

    // ---- epilogue: layer1 step L-1 ----
    float h1a[8];
    {
        uint64_t a1A = fma2(wi1p[0], h0p[0], b1p);
        uint64_t a1B = fma2(wi1p[1], h0p[1], z64);
        a1A = fma2(wi1p[2], h0p[2], a1A);
        a1B = fma2(wi1p[3], h0p[3], a1B);
        a1A = fma2(wh1p[0], h1p[0], a1A);
        a1B = fma2(wh1p[1], h1p[1], a1B);
        a1A = fma2(wh1p[2], h1p[2], a1A);
        a1B = fma2(wh1p[3], h1p[3], a1B);
        float a1 = hadd2(add2(a1A, a1B));
        float g1v = gate_act(a1, kk, mm);
        float fg = __shfl_down_sync(FULLMASK, g1v, 8);
        float gg = __shfl_down_sync(FULLMASK, g1v, 16);
        float og = __shfl_down_sync(FULLMASK, g1v, 24);
        c1 = fmaf(fg, c1, g1v * gg);
        float h1n = og * tanh_acc(c1);
#pragma unroll
        for (int k = 0; k < 8; k++) h1a[k] = __shfl_sync(FULLMASK, h1n, k);
    }

    // ---- heads ----
    float feat[4];
#pragma unroll
    for (int j = 0; j < 4; j++) {
        float a = bl[j];
#pragma unroll
        for (int k = 0; k < 8; k++) a = fmaf(Wl[j * 8 + k], h1a[k], a);
        feat[j] = tanh_acc(a);
    }

    if (lane == 0) {
        float v = bv[0];
#pragma unroll
        for (int j = 0; j < 4; j++) v = fmaf(Wv[j], feat[j], v);
        out[b] = v;                                   // value [B,1]
    }
    if (lane < 4) {
        float m = ba[lane];
#pragma unroll
        for (int j = 0; j < 4; j++) m = fmaf(Wa[lane * 4 + j], feat[j], m);
        out[B + b * 4 + lane] = m;                    // action_mean [B,4]
        float ls = log_std[lane];
        out[5 * B + b * 4 + lane] = ls;               // action_log_std [B,4]
        out[9 * B + b * 4 + lane] = ex2f_(ls * L2E);  // action_std [B,4]
    }
}

extern "C" void kernel_launch(void* const* d_in, const int* in_sizes, int n_in,
                              void* d_out, int out_size)
{
    const float* seq     = (const float*)d_in[0];
    const int*   lengths = (const int*)d_in[1];
    const float* Wih0 = (const float*)d_in[2];
    const float* Whh0 = (const float*)d_in[3];
    const float* bih0 = (const float*)d_in[4];
    const float* bhh0 = (const float*)d_in[5];
    const float* Wih1 = (const float*)d_in[6];
    const float* Whh1 = (const float*)d_in[7];
    const float* bih1 = (const float*)d_in[8];
    const float* bhh1 = (const float*)d_in[9];
    const float* Wl = (const float*)d_in[10];
    const float* bl = (const float*)d_in[11];
    const float* Wv = (const float*)d_in[12];
    const float* bv = (const float*)d_in[13];
    const float* Wa = (const float*)d_in[14];
    const float* ba = (const float*)d_in[15];
    const float* ls = (const float*)d_in[16];
    float* out = (float*)d_out;

    int B = in_sizes[1];
    int S = in_sizes[0] / (B * 8);

    int use_perm = (B <= 4096) ? 1 : 0;
    if (use_perm) {
        int rthreads = 256;
        rank_kernel<<<(B + rthreads - 1) / rthreads, rthreads>>>(lengths, B);
    }

    int threads = 128;                       // 4 warps/CTA, 1 sequence per warp
    int grid = (B * 32 + threads - 1) / threads;
    rnn_ac_kernel<<<grid, threads>>>(seq, lengths, Wih0, Whh0, bih0, bhh0,
                                     Wih1, Whh1, bih1, bhh1,
                                     Wl, bl, Wv, bv, Wa, ba, ls, out, B, S,
                                     use_perm);
}